// round 1
// baseline (speedup 1.0000x reference)
#include <cuda_runtime.h>

#define Nn 100000
#define MAXE 3200000
#define Gg 5000
#define BN_EPS 1e-5f

// ---------------- scratch (static device globals; no dynamic alloc) ----------------
__device__ int      g_deg [Nn];
__device__ float    g_dinv[Nn];
__device__ float    g_t   [Nn * 128];   // reused: t1(64), t2(32), t3(16), xg(128)
__device__ float    g_acc1[Nn * 64];
__device__ float    g_h1  [Nn * 64];
__device__ float    g_acc2[Nn * 32];
__device__ float    g_h2  [Nn * 32];
__device__ float    g_acc3[Nn * 16];
__device__ float    g_h3  [Nn * 16];
__device__ float    g_as  [Nn * 8];
__device__ float    g_ad  [Nn * 8];
__device__ unsigned g_mkey[Nn * 8];
__device__ float    g_ssum[Nn * 8];
__device__ float    g_agg [Nn * 128];
__device__ float    g_pool[Gg * 16];
__device__ float    g_bn  [6 * 64];     // [sum|sumsq] per layer

// ---------------- helpers ----------------
__device__ __forceinline__ void red4(float4* p, float4 v) {
    asm volatile("red.global.add.v4.f32 [%0], {%1,%2,%3,%4};"
                 :: "l"(p), "f"(v.x), "f"(v.y), "f"(v.z), "f"(v.w) : "memory");
}
// monotone float -> uint key (order-preserving incl. negatives); key 0 < all real keys
__device__ __forceinline__ unsigned fkey(float f) {
    unsigned u = __float_as_uint(f);
    return (u & 0x80000000u) ? ~u : (u | 0x80000000u);
}
__device__ __forceinline__ float fdec(unsigned k) {
    return __uint_as_float((k & 0x80000000u) ? (k & 0x7fffffffu) : ~k);
}
__device__ __forceinline__ float leaky(float v) { return v > 0.f ? v : 0.2f * v; }

// ---------------- kernels ----------------
__global__ void k_init() {
    int T = gridDim.x * blockDim.x;
    for (int i = blockIdx.x * blockDim.x + threadIdx.x; i < Nn * 128; i += T) {
        g_agg[i] = 0.f;
        if (i < Nn * 64) g_acc1[i] = 0.f;
        if (i < Nn * 32) g_acc2[i] = 0.f;
        if (i < Nn * 16) g_acc3[i] = 0.f;
        if (i < Nn * 8) { g_mkey[i] = 0u; g_ssum[i] = 0.f; }
        if (i < Nn)      g_deg[i] = 0;
        if (i < Gg * 16) g_pool[i] = 0.f;
        if (i < 6 * 64)  g_bn[i] = 0.f;
    }
}

__global__ void k_deg(const int* __restrict__ ei, int E) {
    int i = blockIdx.x * blockDim.x + threadIdx.x;
    if (i < E) atomicAdd(&g_deg[ei[E + i]], 1);
}
__global__ void k_dinv() {
    int i = blockIdx.x * blockDim.x + threadIdx.x;
    if (i < Nn) g_dinv[i] = rsqrtf((float)(g_deg[i] + 1));  // +1 self loop
}

// out[N,FO] = h[N,FI] @ W[FI,FO]
template <int FI, int FO, int ROWS>
__global__ void k_gemm(const float* __restrict__ h, const float* __restrict__ W,
                       float* __restrict__ out) {
    __shared__ float Ws[FI * FO];
    for (int i = threadIdx.x; i < FI * FO; i += blockDim.x) Ws[i] = W[i];
    __syncthreads();
    int fo = threadIdx.x % FO;
    int r  = threadIdx.x / FO;
    int node = blockIdx.x * ROWS + r;
    if (node >= Nn) return;
    const float* hr = h + node * FI;
    float acc = 0.f;
#pragma unroll
    for (int fi = 0; fi < FI; fi++) acc += hr[fi] * Ws[fi * FO + fo];
    out[node * FO + fo] = acc;
}

// edge scatter: acc[dst] += t[src] * dinv[src]*dinv[dst], vectorized float4
template <int F4>
__global__ void k_scatter(const int* __restrict__ ei, const float4* __restrict__ t4,
                          float4* __restrict__ acc4, int E) {
    int idx = blockIdx.x * blockDim.x + threadIdx.x;
    if (idx >= E * F4) return;
    int e = idx / F4, j = idx % F4;
    int s = ei[e], d = ei[E + e];
    float nm = g_dinv[s] * g_dinv[d];
    float4 v = t4[s * F4 + j];
    v.x *= nm; v.y *= nm; v.z *= nm; v.w *= nm;
    red4(&acc4[d * F4 + j], v);
}

// self-loop contribution + bias
template <int F>
__global__ void k_selfbias(const float* __restrict__ t, float* __restrict__ acc,
                           const float* __restrict__ b) {
    int i = blockIdx.x * blockDim.x + threadIdx.x;
    if (i >= Nn * F) return;
    int node = i / F, f = i % F;
    float dv = g_dinv[node];
    acc[i] += t[i] * dv * dv + b[f];
}

// per-feature sum and sumsq; T must be a multiple of F so each thread owns one column
template <int F>
__global__ void k_stats(const float* __restrict__ acc, float* __restrict__ stat) {
    int T = gridDim.x * blockDim.x;
    int gtid = blockIdx.x * blockDim.x + threadIdx.x;
    int f = gtid % F;
    float s = 0.f, q = 0.f;
    for (int i = gtid; i < Nn * F; i += T) { float v = acc[i]; s += v; q += v * v; }
    atomicAdd(&stat[f], s);
    atomicAdd(&stat[F + f], q);
}

template <int F>
__global__ void k_bnrelu(const float* __restrict__ acc, const float* __restrict__ stat,
                         const float* __restrict__ g, const float* __restrict__ be,
                         float* __restrict__ out) {
    int i = blockIdx.x * blockDim.x + threadIdx.x;
    if (i >= Nn * F) return;
    int f = i % F;
    const float invn = 1.0f / (float)Nn;
    float mu  = stat[f] * invn;
    float var = stat[F + f] * invn - mu * mu;
    float v = (acc[i] - mu) * rsqrtf(var + BN_EPS) * g[f] + be[f];
    out[i] = fmaxf(v, 0.f);
}

__global__ void k_attdot(const float* __restrict__ xg, const float* __restrict__ asrc,
                         const float* __restrict__ adst) {
    int i = blockIdx.x * blockDim.x + threadIdx.x;
    if (i >= Nn * 8) return;
    int node = i >> 3, h = i & 7;
    const float* p = xg + node * 128 + h * 16;
    float s1 = 0.f, s2 = 0.f;
#pragma unroll
    for (int c = 0; c < 16; c++) { s1 += p[c] * asrc[h * 16 + c]; s2 += p[c] * adst[h * 16 + c]; }
    g_as[i] = s1;
    g_ad[i] = s2;
}

// segment max over dst (incl. self loops as items >= E)
__global__ void k_max(const int* __restrict__ ei, int E) {
    int item = blockIdx.x * blockDim.x + threadIdx.x;
    if (item >= E + Nn) return;
    int s, d;
    if (item < E) { s = ei[item]; d = ei[E + item]; } else { s = d = item - E; }
#pragma unroll
    for (int h = 0; h < 8; h++) {
        float l = leaky(g_as[s * 8 + h] + g_ad[d * 8 + h]);
        atomicMax(&g_mkey[d * 8 + h], fkey(l));
    }
}

__global__ void k_esum(const int* __restrict__ ei, int E) {
    int item = blockIdx.x * blockDim.x + threadIdx.x;
    if (item >= E + Nn) return;
    int s, d;
    if (item < E) { s = ei[item]; d = ei[E + item]; } else { s = d = item - E; }
#pragma unroll
    for (int h = 0; h < 8; h++) {
        float l = leaky(g_as[s * 8 + h] + g_ad[d * 8 + h]);
        float m = fdec(g_mkey[d * 8 + h]);
        atomicAdd(&g_ssum[d * 8 + h], __expf(l - m));
    }
}

// weighted aggregation: agg[dst] += xg[src] * alpha, 32 float4 lanes per item
__global__ void k_agg(const int* __restrict__ ei, const float4* __restrict__ xg4, int E) {
    int i = blockIdx.x * blockDim.x + threadIdx.x;
    int item = i >> 5;
    if (item >= E + Nn) return;
    int j = i & 31, h = j >> 2;
    int s, d;
    if (item < E) { s = ei[item]; d = ei[E + item]; } else { s = d = item - E; }
    float l = leaky(g_as[s * 8 + h] + g_ad[d * 8 + h]);
    float m = fdec(g_mkey[d * 8 + h]);
    float alpha = __expf(l - m) / g_ssum[d * 8 + h];
    float4 v = xg4[s * 32 + j];
    v.x *= alpha; v.y *= alpha; v.z *= alpha; v.w *= alpha;
    red4(((float4*)g_agg) + d * 32 + j, v);
}

// mean over heads + bg, then add-pool into graphs
__global__ void k_pool(const int* __restrict__ batch, const float* __restrict__ bg) {
    int i = blockIdx.x * blockDim.x + threadIdx.x;
    if (i >= Nn * 16) return;
    int node = i >> 4, c = i & 15;
    float s = 0.f;
#pragma unroll
    for (int h = 0; h < 8; h++) s += g_agg[node * 128 + h * 16 + c];
    float hgv = s * 0.125f + bg[c];
    atomicAdd(&g_pool[batch[node] * 16 + c], hgv);
}

__global__ void k_final(const float* __restrict__ Wf, const float* __restrict__ bf,
                        float* __restrict__ out) {
    int i = blockIdx.x * blockDim.x + threadIdx.x;
    if (i >= Gg * 3) return;
    int gg = i / 3, k = i % 3;
    float s = bf[k];
#pragma unroll
    for (int c = 0; c < 16; c++) s += g_pool[gg * 16 + c] * Wf[c * 3 + k];
    out[i] = s;
}

// ---------------- launch ----------------
static inline void* symaddr(const void* s) { void* p = nullptr; cudaGetSymbolAddress(&p, s); return p; }

extern "C" void kernel_launch(void* const* d_in, const int* in_sizes, int n_in,
                              void* d_out, int out_size) {
    const float* x       = (const float*)d_in[0];
    const int*   ei      = (const int*)  d_in[1];
    const int*   batch   = (const int*)  d_in[2];
    const float* W1 = (const float*)d_in[3],  *b1 = (const float*)d_in[4];
    const float* g1 = (const float*)d_in[5],  *be1= (const float*)d_in[6];
    const float* W2 = (const float*)d_in[7],  *b2 = (const float*)d_in[8];
    const float* g2 = (const float*)d_in[9],  *be2= (const float*)d_in[10];
    const float* W3 = (const float*)d_in[11], *b3 = (const float*)d_in[12];
    const float* g3 = (const float*)d_in[13], *be3= (const float*)d_in[14];
    const float* Wg = (const float*)d_in[15];
    const float* att_src = (const float*)d_in[16];
    const float* att_dst = (const float*)d_in[17];
    const float* bg = (const float*)d_in[18];
    const float* Wf = (const float*)d_in[19], *bf = (const float*)d_in[20];
    float* out = (float*)d_out;
    const int E = in_sizes[1] / 2;

    float* t    = (float*)symaddr(g_t);
    float* acc1 = (float*)symaddr(g_acc1);
    float* h1   = (float*)symaddr(g_h1);
    float* acc2 = (float*)symaddr(g_acc2);
    float* h2   = (float*)symaddr(g_h2);
    float* acc3 = (float*)symaddr(g_acc3);
    float* h3   = (float*)symaddr(g_h3);
    float* bn   = (float*)symaddr(g_bn);

    const int B = 256;
    k_init<<<(Nn * 128 + B - 1) / B, B>>>();
    k_deg<<<(E + B - 1) / B, B>>>(ei, E);
    k_dinv<<<(Nn + B - 1) / B, B>>>();

    // ---- GCN layer 1: 20 -> 64 ----
    k_gemm<20, 64, 4><<<(Nn + 3) / 4, B>>>(x, W1, t);
    k_scatter<16><<<(E * 16 + B - 1) / B, B>>>(ei, (const float4*)t, (float4*)acc1, E);
    k_selfbias<64><<<(Nn * 64 + B - 1) / B, B>>>(t, acc1, b1);
    k_stats<64><<<64, B>>>(acc1, bn + 0);
    k_bnrelu<64><<<(Nn * 64 + B - 1) / B, B>>>(acc1, bn + 0, g1, be1, h1);

    // ---- GCN layer 2: 64 -> 32 ----
    k_gemm<64, 32, 8><<<(Nn + 7) / 8, B>>>(h1, W2, t);
    k_scatter<8><<<(E * 8 + B - 1) / B, B>>>(ei, (const float4*)t, (float4*)acc2, E);
    k_selfbias<32><<<(Nn * 32 + B - 1) / B, B>>>(t, acc2, b2);
    k_stats<32><<<64, B>>>(acc2, bn + 128);
    k_bnrelu<32><<<(Nn * 32 + B - 1) / B, B>>>(acc2, bn + 128, g2, be2, h2);

    // ---- GCN layer 3: 32 -> 16 ----
    k_gemm<32, 16, 16><<<(Nn + 15) / 16, B>>>(h2, W3, t);
    k_scatter<4><<<(E * 4 + B - 1) / B, B>>>(ei, (const float4*)t, (float4*)acc3, E);
    k_selfbias<16><<<(Nn * 16 + B - 1) / B, B>>>(t, acc3, b3);
    k_stats<16><<<64, B>>>(acc3, bn + 256);
    k_bnrelu<16><<<(Nn * 16 + B - 1) / B, B>>>(acc3, bn + 256, g3, be3, h3);

    // ---- GAT: xg = h3 @ Wg [N,8,16] ----
    k_gemm<16, 128, 2><<<(Nn + 1) / 2, B>>>(h3, Wg, t);
    k_attdot<<<(Nn * 8 + B - 1) / B, B>>>(t, att_src, att_dst);
    k_max<<<(E + Nn + B - 1) / B, B>>>(ei, E);
    k_esum<<<(E + Nn + B - 1) / B, B>>>(ei, E);
    k_agg<<<((E + Nn) * 32 + B - 1) / B, B>>>(ei, (const float4*)t, E);

    // ---- pool + classifier ----
    k_pool<<<(Nn * 16 + B - 1) / B, B>>>(batch, bg);
    k_final<<<(Gg * 3 + B - 1) / B, B>>>(Wf, bf, out);
}

// round 3
// speedup vs baseline: 2.1597x; 2.1597x over previous
#include <cuda_runtime.h>

#define Nn 100000
#define MAXE 3200000
#define Gg 5000
#define BN_EPS 1e-5f

// ---------------- scratch (static device globals) ----------------
__device__ int      g_deg [Nn];
__device__ int      g_row [Nn + 1];
__device__ int      g_cur [Nn];
__device__ int      g_csrc[MAXE];
__device__ float    g_dinv[Nn];
__device__ float    g_t   [Nn * 128];   // reused: t1(64), t2(32), t3(16), xg(128)
__device__ float    g_acc1[Nn * 64];
__device__ float    g_h1  [Nn * 64];
__device__ float    g_acc2[Nn * 32];
__device__ float    g_h2  [Nn * 32];
__device__ float    g_acc3[Nn * 16];
__device__ float    g_h3  [Nn * 16];
__device__ float    g_as  [Nn * 8];
__device__ float    g_ad  [Nn * 8];
__device__ float    g_pool[Gg * 16];
__device__ float    g_bn  [6 * 64];     // [sum|sumsq] per layer

// ---------------- helpers ----------------
__device__ __forceinline__ void red4(float4* p, float4 v) {
    asm volatile("red.global.add.v4.f32 [%0], {%1,%2,%3,%4};"
                 :: "l"(p), "f"(v.x), "f"(v.y), "f"(v.z), "f"(v.w) : "memory");
}
__device__ __forceinline__ float leaky(float v) { return v > 0.f ? v : 0.2f * v; }

// ---------------- kernels ----------------
__global__ void k_init() {
    int T = gridDim.x * blockDim.x;
    for (int i = blockIdx.x * blockDim.x + threadIdx.x; i < Nn; i += T) {
        g_deg[i] = 0;
        if (i < Gg * 16) g_pool[i] = 0.f;
        if (i < 6 * 64)  g_bn[i] = 0.f;
    }
}

__global__ void k_deg(const int* __restrict__ ei, int E) {
    int i = blockIdx.x * blockDim.x + threadIdx.x;
    if (i < E) atomicAdd(&g_deg[ei[E + i]], 1);
}

// single-block scan over g_deg -> g_row (exclusive), also g_cur = g_row, g_dinv
__global__ void k_scan() {
    __shared__ int sh[1024];
    const int CH = (Nn + 1023) / 1024;
    int t = threadIdx.x;
    int base = t * CH;
    int s = 0;
    for (int i = 0; i < CH; i++) {
        int idx = base + i;
        if (idx < Nn) s += g_deg[idx];
    }
    sh[t] = s;
    __syncthreads();
    for (int off = 1; off < 1024; off <<= 1) {
        int v = (t >= off) ? sh[t - off] : 0;
        __syncthreads();
        sh[t] += v;
        __syncthreads();
    }
    int run = (t == 0) ? 0 : sh[t - 1];
    for (int i = 0; i < CH; i++) {
        int idx = base + i;
        if (idx < Nn) {
            g_row[idx] = run;
            g_cur[idx] = run;
            g_dinv[idx] = rsqrtf((float)(g_deg[idx] + 1));  // +1 self loop
            run += g_deg[idx];
        }
    }
    if (t == 1023) g_row[Nn] = run;
}

__global__ void k_fill(const int* __restrict__ ei, int E) {
    int e = blockIdx.x * blockDim.x + threadIdx.x;
    if (e >= E) return;
    int s = ei[e], d = ei[E + e];
    int p = atomicAdd(&g_cur[d], 1);
    g_csrc[p] = s;
}

// out[N,FO] = h[N,FI] @ W[FI,FO]
template <int FI, int FO, int BLK>
__global__ void k_gemm(const float* __restrict__ h, const float* __restrict__ W,
                       float* __restrict__ out) {
    __shared__ float Ws[FI * FO];
    for (int i = threadIdx.x; i < FI * FO; i += BLK) Ws[i] = W[i];
    __syncthreads();
    const int ROWS = BLK / FO;
    int fo = threadIdx.x % FO;
    int r  = threadIdx.x / FO;
    int node = blockIdx.x * ROWS + r;
    if (node >= Nn) return;
    const float* hr = h + node * FI;
    float acc = 0.f;
#pragma unroll
    for (int fi = 0; fi < FI; fi++) acc += hr[fi] * Ws[fi * FO + fo];
    out[node * FO + fo] = acc;
}

// CSR gather GCN: acc[d] = sum_{s in adj(d)} t[s]*dinv[s]*dinv[d] + t[d]*dinv[d]^2 + b
// group of F4 lanes per node, 32/F4 nodes per warp
template <int F4>
__global__ void k_gcn(const float4* __restrict__ t4, const float* __restrict__ b,
                      float4* __restrict__ out4) {
    const int GPW = 32 / F4;
    int lane = threadIdx.x & 31, warp = threadIdx.x >> 5;
    int grp = lane / F4, j = lane % F4;
    int node = (blockIdx.x * (blockDim.x >> 5) + warp) * GPW + grp;
    if (node >= Nn) return;
    float di = g_dinv[node];
    int r0 = g_row[node], r1 = g_row[node + 1];
    float4 sv = t4[node * F4 + j];
    float ns = di * di;
    float4 acc = make_float4(sv.x * ns, sv.y * ns, sv.z * ns, sv.w * ns);
    for (int k = r0; k < r1; k++) {
        int s = g_csrc[k];
        float nm = di * g_dinv[s];
        float4 v = t4[s * F4 + j];
        acc.x += v.x * nm; acc.y += v.y * nm; acc.z += v.z * nm; acc.w += v.w * nm;
    }
    float4 bb = ((const float4*)b)[j];
    acc.x += bb.x; acc.y += bb.y; acc.z += bb.z; acc.w += bb.w;
    out4[node * F4 + j] = acc;
}

// per-feature sum and sumsq; total threads must be a multiple of F
template <int F>
__global__ void k_stats(const float* __restrict__ acc, float* __restrict__ stat) {
    int T = gridDim.x * blockDim.x;
    int gtid = blockIdx.x * blockDim.x + threadIdx.x;
    int f = gtid % F;
    float s = 0.f, q = 0.f;
    for (int i = gtid; i < Nn * F; i += T) { float v = acc[i]; s += v; q += v * v; }
    atomicAdd(&stat[f], s);
    atomicAdd(&stat[F + f], q);
}

template <int F>
__global__ void k_bnrelu(const float* __restrict__ acc, const float* __restrict__ stat,
                         const float* __restrict__ g, const float* __restrict__ be,
                         float* __restrict__ out) {
    int i = blockIdx.x * blockDim.x + threadIdx.x;
    if (i >= Nn * F) return;
    int f = i % F;
    const float invn = 1.0f / (float)Nn;
    float mu  = stat[f] * invn;
    float var = stat[F + f] * invn - mu * mu;
    float v = (acc[i] - mu) * rsqrtf(var + BN_EPS) * g[f] + be[f];
    out[i] = fmaxf(v, 0.f);
}

__global__ void k_attdot(const float* __restrict__ xg, const float* __restrict__ asrc,
                         const float* __restrict__ adst) {
    int i = blockIdx.x * blockDim.x + threadIdx.x;
    if (i >= Nn * 8) return;
    int node = i >> 3, h = i & 7;
    const float* p = xg + node * 128 + h * 16;
    float s1 = 0.f, s2 = 0.f;
#pragma unroll
    for (int c = 0; c < 16; c++) { s1 += p[c] * asrc[h * 16 + c]; s2 += p[c] * adst[h * 16 + c]; }
    g_as[i] = s1;
    g_ad[i] = s2;
}

// Fused GAT: warp per dst node. Register softmax (max pass + exp-sum pass),
// weighted gather, head-mean, + graph add-pool. No global atomics except pool.
__global__ void k_gat(const float4* __restrict__ xg4, const float* __restrict__ bg,
                      const int* __restrict__ batch) {
    int lane = threadIdx.x & 31, warp = threadIdx.x >> 5;
    int d = blockIdx.x * (blockDim.x >> 5) + warp;
    if (d >= Nn) return;
    int h = lane >> 2;
    float adh = g_ad[d * 8 + h];
    float asd = g_as[d * 8 + h];
    int r0 = g_row[d], r1 = g_row[d + 1];

    // pass 1: per-head max over incident edges (+self)
    float m = leaky(asd + adh);
    for (int k = r0; k < r1; k++) {
        int s = g_csrc[k];
        m = fmaxf(m, leaky(g_as[s * 8 + h] + adh));
    }
    // pass 2: sum-exp and weighted feature accumulation together
    float e0 = __expf(leaky(asd + adh) - m);
    float4 xv = xg4[d * 32 + lane];
    float4 acc = make_float4(xv.x * e0, xv.y * e0, xv.z * e0, xv.w * e0);
    float sum = e0;
    for (int k = r0; k < r1; k++) {
        int s = g_csrc[k];
        float e = __expf(leaky(g_as[s * 8 + h] + adh) - m);
        sum += e;
        float4 v = xg4[s * 32 + lane];
        acc.x += e * v.x; acc.y += e * v.y; acc.z += e * v.z; acc.w += e * v.w;
    }
    float sc = 0.125f / sum;  // alpha-normalize + head-mean in one scale
    acc.x *= sc; acc.y *= sc; acc.z *= sc; acc.w *= sc;

    // reduce over the 8 heads (lanes with equal lane&3)
#pragma unroll
    for (int off = 4; off < 32; off <<= 1) {
        acc.x += __shfl_xor_sync(~0u, acc.x, off);
        acc.y += __shfl_xor_sync(~0u, acc.y, off);
        acc.z += __shfl_xor_sync(~0u, acc.z, off);
        acc.w += __shfl_xor_sync(~0u, acc.w, off);
    }
    if (lane < 4) {
        float4 bgv = ((const float4*)bg)[lane];
        acc.x += bgv.x; acc.y += bgv.y; acc.z += bgv.z; acc.w += bgv.w;
        red4(((float4*)g_pool) + batch[d] * 4 + lane, acc);
    }
}

__global__ void k_final(const float* __restrict__ Wf, const float* __restrict__ bf,
                        float* __restrict__ out) {
    int i = blockIdx.x * blockDim.x + threadIdx.x;
    if (i >= Gg * 3) return;
    int gg = i / 3, k = i % 3;
    float s = bf[k];
#pragma unroll
    for (int c = 0; c < 16; c++) s += g_pool[gg * 16 + c] * Wf[c * 3 + k];
    out[i] = s;
}

// ---------------- launch ----------------
static inline void* symaddr(const void* s) { void* p = nullptr; cudaGetSymbolAddress(&p, s); return p; }

extern "C" void kernel_launch(void* const* d_in, const int* in_sizes, int n_in,
                              void* d_out, int out_size) {
    const float* x       = (const float*)d_in[0];
    const int*   ei      = (const int*)  d_in[1];
    const int*   batch   = (const int*)  d_in[2];
    const float* W1 = (const float*)d_in[3],  *b1 = (const float*)d_in[4];
    const float* g1 = (const float*)d_in[5],  *be1= (const float*)d_in[6];
    const float* W2 = (const float*)d_in[7],  *b2 = (const float*)d_in[8];
    const float* g2 = (const float*)d_in[9],  *be2= (const float*)d_in[10];
    const float* W3 = (const float*)d_in[11], *b3 = (const float*)d_in[12];
    const float* g3 = (const float*)d_in[13], *be3= (const float*)d_in[14];
    const float* Wg = (const float*)d_in[15];
    const float* att_src = (const float*)d_in[16];
    const float* att_dst = (const float*)d_in[17];
    const float* bg = (const float*)d_in[18];
    const float* Wf = (const float*)d_in[19], *bf = (const float*)d_in[20];
    float* out = (float*)d_out;
    const int E = in_sizes[1] / 2;

    float* t    = (float*)symaddr(g_t);
    float* acc1 = (float*)symaddr(g_acc1);
    float* h1   = (float*)symaddr(g_h1);
    float* acc2 = (float*)symaddr(g_acc2);
    float* h2   = (float*)symaddr(g_h2);
    float* acc3 = (float*)symaddr(g_acc3);
    float* h3   = (float*)symaddr(g_h3);
    float* bn   = (float*)symaddr(g_bn);

    const int B = 256;
    // ---- CSR build ----
    k_init<<<(Nn + B - 1) / B, B>>>();
    k_deg<<<(E + B - 1) / B, B>>>(ei, E);
    k_scan<<<1, 1024>>>();
    k_fill<<<(E + B - 1) / B, B>>>(ei, E);

    // ---- GCN layer 1: 20 -> 64 ----
    k_gemm<20, 64, 512><<<(Nn + 7) / 8, 512>>>(x, W1, t);
    k_gcn<16><<<(Nn + 15) / 16, B>>>((const float4*)t, b1, (float4*)acc1);
    k_stats<64><<<512, B>>>(acc1, bn + 0);
    k_bnrelu<64><<<(Nn * 64 + B - 1) / B, B>>>(acc1, bn + 0, g1, be1, h1);

    // ---- GCN layer 2: 64 -> 32 ----
    k_gemm<64, 32, 512><<<(Nn + 15) / 16, 512>>>(h1, W2, t);
    k_gcn<8><<<(Nn + 31) / 32, B>>>((const float4*)t, b2, (float4*)acc2);
    k_stats<32><<<512, B>>>(acc2, bn + 128);
    k_bnrelu<32><<<(Nn * 32 + B - 1) / B, B>>>(acc2, bn + 128, g2, be2, h2);

    // ---- GCN layer 3: 32 -> 16 ----
    k_gemm<32, 16, 512><<<(Nn + 31) / 32, 512>>>(h2, W3, t);
    k_gcn<4><<<(Nn + 63) / 64, B>>>((const float4*)t, b3, (float4*)acc3);
    k_stats<16><<<512, B>>>(acc3, bn + 256);
    k_bnrelu<16><<<(Nn * 16 + B - 1) / B, B>>>(acc3, bn + 256, g3, be3, h3);

    // ---- GAT: xg = h3 @ Wg [N,8,16] ----
    k_gemm<16, 128, 512><<<(Nn + 3) / 4, 512>>>(h3, Wg, t);
    k_attdot<<<(Nn * 8 + B - 1) / B, B>>>(t, att_src, att_dst);
    k_gat<<<(Nn + 7) / 8, B>>>((const float4*)t, bg, batch);

    // ---- classifier ----
    k_final<<<(Gg * 3 + B - 1) / B, B>>>(Wf, bf, out);
}